// round 2
// baseline (speedup 1.0000x reference)
#include <cuda_runtime.h>
#include <cstdint>

#define B_ROWS 8192
#define L_DIM  4096
#define OUT_DIM 512
#define SQRT_HALF 0.7071067811865476f

// ---------------- scratch (static __device__, no allocation) ----------------
__device__ float  g_F[(size_t)B_ROWS * L_DIM];   // 128 MB coefficient matrix
__device__ double g_pabs[B_ROWS];
__device__ double g_psq[B_ROWS];
__device__ float  g_thr;

// ---------------- packed f32x2 helpers ----------------
__device__ __forceinline__ unsigned long long rep2(float a) {
    unsigned long long r;
    asm("mov.b64 %0, {%1, %1};" : "=l"(r) : "f"(a));
    return r;
}
__device__ __forceinline__ void ffma2(unsigned long long& c,
                                      unsigned long long a,
                                      unsigned long long b) {
    asm("fma.rn.f32x2 %0, %1, %2, %3;" : "=l"(c) : "l"(a), "l"(b), "l"(c));
}

// ---------------- kernel 1: Haar DWT + per-row stats ----------------
__global__ __launch_bounds__(256) void haar_kernel(const float* __restrict__ x) {
    __shared__ float s[4096];
    __shared__ double wa[8], wq[8];

    const int r = blockIdx.x;
    const int tid = threadIdx.x;

    const float4* xr = reinterpret_cast<const float4*>(x + (size_t)r * L_DIM);
    float4* s4 = reinterpret_cast<float4*>(s);
    #pragma unroll
    for (int i = 0; i < 4; i++) s4[tid + i * 256] = xr[tid + i * 256];
    __syncthreads();

    float sabs = 0.f, ssq = 0.f;
    float* Fr = g_F + (size_t)r * L_DIM;

    #pragma unroll
    for (int lvl = 0; lvl < 5; lvl++) {
        const int half = 2048 >> lvl;           // #coeffs this level == concat offset of cD
        float areg[8];
        #pragma unroll
        for (int it = 0; it < 8; it++) {
            const int t = tid + it * 256;
            if (t < half) {
                float2 eo = *reinterpret_cast<const float2*>(&s[2 * t]);
                float d = (eo.x - eo.y) * SQRT_HALF;
                float a = (eo.x + eo.y) * SQRT_HALF;
                Fr[half + t] = d;
                sabs += fabsf(d);
                ssq  += d * d;
                areg[it] = a;
            }
        }
        __syncthreads();
        #pragma unroll
        for (int it = 0; it < 8; it++) {
            const int t = tid + it * 256;
            if (t < half) s[t] = areg[it];
        }
        __syncthreads();
    }
    if (tid < 128) {                            // cA5 at offset 0
        float a = s[tid];
        Fr[tid] = a;
        sabs += fabsf(a);
        ssq  += a * a;
    }

    double da = (double)sabs, dq = (double)ssq;
    #pragma unroll
    for (int o = 16; o > 0; o >>= 1) {
        da += __shfl_down_sync(0xffffffffu, da, o);
        dq += __shfl_down_sync(0xffffffffu, dq, o);
    }
    const int w = tid >> 5, ln = tid & 31;
    if (ln == 0) { wa[w] = da; wq[w] = dq; }
    __syncthreads();
    if (tid == 0) {
        double A = 0.0, Q = 0.0;
        #pragma unroll
        for (int i = 0; i < 8; i++) { A += wa[i]; Q += wq[i]; }
        g_pabs[r] = A;
        g_psq[r]  = Q;
    }
}

// ---------------- kernel 2: global threshold (deterministic order) ----------------
__global__ __launch_bounds__(256) void thr_kernel() {
    __shared__ double wa[8], wq[8];
    const int tid = threadIdx.x;
    double da = 0.0, dq = 0.0;
    for (int i = tid; i < B_ROWS; i += 256) { da += g_pabs[i]; dq += g_psq[i]; }
    #pragma unroll
    for (int o = 16; o > 0; o >>= 1) {
        da += __shfl_down_sync(0xffffffffu, da, o);
        dq += __shfl_down_sync(0xffffffffu, dq, o);
    }
    const int w = tid >> 5, ln = tid & 31;
    if (ln == 0) { wa[w] = da; wq[w] = dq; }
    __syncthreads();
    if (tid == 0) {
        double A = 0.0, Q = 0.0;
        #pragma unroll
        for (int i = 0; i < 8; i++) { A += wa[i]; Q += wq[i]; }
        const double N = (double)B_ROWS * (double)L_DIM;
        double mean = A / N;
        double var  = (Q - N * mean * mean) / (N - 1.0);
        if (var < 0.0) var = 0.0;
        g_thr = (float)(mean + sqrt(var));   // STD_FACTOR = 1.0
    }
}

// ---------------- kernel 3: masked GEMM + ReLU (packed f32x2 FFMA) ----------------
// C[8192,512] = relu( mask(F) @ Bmat ), 128x128x8 tiles.
// Per-thread 8x8 fragment in SPLIT layout: m in {ty*4+i, 64+ty*4+i},
// n in {tx*4+j, 64+tx*4+j}  -> all LDS.128 are conflict-free (stride-4-word lanes).
__global__ __launch_bounds__(256, 2) void gemm_kernel(const float* __restrict__ Bm,
                                                      float* __restrict__ out) {
    __shared__ float As[8][128];   // [k][m]
    __shared__ float Bs[8][128];   // [k][n]

    const float thr = g_thr;
    const int bm = blockIdx.y * 128;
    const int bn = blockIdx.x * 128;
    const int tid = threadIdx.x;
    const int tx = tid & 15, ty = tid >> 4;

    const int arow = tid >> 1;
    const int acol = (tid & 1) * 4;
    const int brow = tid >> 5;
    const int bcol = (tid & 31) * 4;

    const float* Ap = g_F + (size_t)(bm + arow) * L_DIM + acol;
    const float* Bp = Bm + (size_t)brow * OUT_DIM + bn + bcol;

    unsigned long long c2[8][4];
    #pragma unroll
    for (int i = 0; i < 8; i++)
        #pragma unroll
        for (int j = 0; j < 4; j++) c2[i][j] = 0ull;

    float4 av = *reinterpret_cast<const float4*>(Ap);
    float4 bv = *reinterpret_cast<const float4*>(Bp);

    int k0 = 0;
    for (;;) {
        // mask A fragment, stage tiles
        av.x = (fabsf(av.x) > thr) ? av.x : 0.f;
        av.y = (fabsf(av.y) > thr) ? av.y : 0.f;
        av.z = (fabsf(av.z) > thr) ? av.z : 0.f;
        av.w = (fabsf(av.w) > thr) ? av.w : 0.f;
        As[acol + 0][arow] = av.x;
        As[acol + 1][arow] = av.y;
        As[acol + 2][arow] = av.z;
        As[acol + 3][arow] = av.w;
        *reinterpret_cast<float4*>(&Bs[brow][bcol]) = bv;
        __syncthreads();

        k0 += 8;
        const bool more = (k0 < L_DIM);
        if (more) {
            av = *reinterpret_cast<const float4*>(Ap + k0);
            bv = *reinterpret_cast<const float4*>(Bp + (size_t)k0 * OUT_DIM);
        }

        #pragma unroll
        for (int k = 0; k < 8; k++) {
            union { float4 f[2]; float x[8]; } au;
            au.f[0] = *reinterpret_cast<const float4*>(&As[k][ty * 4]);        // m: ty*4..+3
            au.f[1] = *reinterpret_cast<const float4*>(&As[k][64 + ty * 4]);   // m: 64+ty*4..+3
            union { float4 f[2]; unsigned long long u[4]; } bu;
            bu.f[0] = *reinterpret_cast<const float4*>(&Bs[k][tx * 4]);        // n: tx*4..+3
            bu.f[1] = *reinterpret_cast<const float4*>(&Bs[k][64 + tx * 4]);   // n: 64+tx*4..+3
            #pragma unroll
            for (int i = 0; i < 8; i++) {
                unsigned long long a2 = rep2(au.x[i]);
                ffma2(c2[i][0], a2, bu.u[0]);   // n = tx*4 + {0,1}
                ffma2(c2[i][1], a2, bu.u[1]);   // n = tx*4 + {2,3}
                ffma2(c2[i][2], a2, bu.u[2]);   // n = 64+tx*4 + {0,1}
                ffma2(c2[i][3], a2, bu.u[3]);   // n = 64+tx*4 + {2,3}
            }
        }
        __syncthreads();
        if (!more) break;
    }

    // epilogue: relu + store
    #pragma unroll
    for (int i = 0; i < 8; i++) {
        const int m = bm + ((i < 4) ? (ty * 4 + i) : (64 + ty * 4 + (i - 4)));
        float* orow = out + (size_t)m * OUT_DIM + bn;
        #pragma unroll
        for (int j = 0; j < 4; j++) {
            const int n = ((j < 2) ? (tx * 4 + 2 * j) : (64 + tx * 4 + 2 * (j - 2)));
            float2 v;
            asm("mov.b64 {%0, %1}, %2;" : "=f"(v.x), "=f"(v.y) : "l"(c2[i][j]));
            v.x = fmaxf(v.x, 0.f);
            v.y = fmaxf(v.y, 0.f);
            *reinterpret_cast<float2*>(&orow[n]) = v;
        }
    }
}

// ---------------- launcher ----------------
extern "C" void kernel_launch(void* const* d_in, const int* in_sizes, int n_in,
                              void* d_out, int out_size) {
    const float* x  = (const float*)d_in[0];     // (8192, 1, 4096) fp32
    const float* bm = (const float*)d_in[1];     // (4096, 512) fp32
    float* out = (float*)d_out;                  // (8192, 1, 512) fp32

    haar_kernel<<<B_ROWS, 256>>>(x);
    thr_kernel<<<1, 256>>>();
    dim3 grid(OUT_DIM / 128, B_ROWS / 128);      // (4, 64)
    gemm_kernel<<<grid, 256>>>(bm, out);
}

// round 5
// speedup vs baseline: 1.5877x; 1.5877x over previous
#include <cuda_runtime.h>
#include <cuda_bf16.h>
#include <cstdint>

#define B_ROWS 8192
#define L_DIM  4096
#define OUT_DIM 512
#define SQRT_HALF 0.7071067811865476f

// ---------------- scratch (static __device__, no allocation) ----------------
__device__ __align__(128) float g_F[(size_t)B_ROWS * L_DIM];            // fp32 coefficients
__device__ __align__(128) __nv_bfloat16 g_Bh[(size_t)OUT_DIM * L_DIM]; // B^T hi [n][k]
__device__ __align__(128) __nv_bfloat16 g_Bl[(size_t)OUT_DIM * L_DIM]; // B^T lo [n][k]
__device__ double g_pabs[B_ROWS];
__device__ double g_psq[B_ROWS];
__device__ float  g_thr;

// ---------------- PTX helpers (sm_80-baseline only; NO 'a' features) ----------------
__device__ __forceinline__ uint32_t smem_u32(const void* p) {
    uint32_t a;
    asm("{ .reg .u64 t; cvta.to.shared.u64 t, %1; cvt.u32.u64 %0, t; }" : "=r"(a) : "l"(p));
    return a;
}
__device__ __forceinline__ void cp16(uint32_t dst, const void* src) {
    asm volatile("cp.async.cg.shared.global [%0], [%1], 16;" :: "r"(dst), "l"(src) : "memory");
}
__device__ __forceinline__ void ldsm4(uint32_t* r, uint32_t addr) {
    asm volatile("ldmatrix.sync.aligned.m8n8.x4.shared.b16 {%0,%1,%2,%3}, [%4];"
                 : "=r"(r[0]), "=r"(r[1]), "=r"(r[2]), "=r"(r[3]) : "r"(addr));
}
__device__ __forceinline__ void mma16816(float* c, const uint32_t* a, const uint32_t* b) {
    asm volatile("mma.sync.aligned.m16n8k16.row.col.f32.bf16.bf16.f32 "
                 "{%0,%1,%2,%3}, {%4,%5,%6,%7}, {%8,%9}, {%0,%1,%2,%3};"
                 : "+f"(c[0]), "+f"(c[1]), "+f"(c[2]), "+f"(c[3])
                 : "r"(a[0]), "r"(a[1]), "r"(a[2]), "r"(a[3]), "r"(b[0]), "r"(b[1]));
}
__device__ __forceinline__ uint32_t pack_bf16(float a, float b) {
    __nv_bfloat16 ha = __float2bfloat16(a), hb = __float2bfloat16(b);
    return ((uint32_t)__bfloat16_as_ushort(hb) << 16) | __bfloat16_as_ushort(ha);
}

// ---------------- kernel 1: Haar DWT + per-row stats ----------------
__global__ __launch_bounds__(256) void haar_kernel(const float* __restrict__ x) {
    __shared__ float s[4096];
    __shared__ double wa[8], wq[8];

    const int r = blockIdx.x;
    const int tid = threadIdx.x;

    const float4* xr = reinterpret_cast<const float4*>(x + (size_t)r * L_DIM);
    float4* s4 = reinterpret_cast<float4*>(s);
    #pragma unroll
    for (int i = 0; i < 4; i++) s4[tid + i * 256] = xr[tid + i * 256];
    __syncthreads();

    float sabs = 0.f, ssq = 0.f;
    float* Fr = g_F + (size_t)r * L_DIM;

    #pragma unroll
    for (int lvl = 0; lvl < 5; lvl++) {
        const int half = 2048 >> lvl;
        float areg[8];
        #pragma unroll
        for (int it = 0; it < 8; it++) {
            const int t = tid + it * 256;
            if (t < half) {
                float2 eo = *reinterpret_cast<const float2*>(&s[2 * t]);
                float d = (eo.x - eo.y) * SQRT_HALF;
                float a = (eo.x + eo.y) * SQRT_HALF;
                Fr[half + t] = d;
                sabs += fabsf(d);
                ssq  += d * d;
                areg[it] = a;
            }
        }
        __syncthreads();
        #pragma unroll
        for (int it = 0; it < 8; it++) {
            const int t = tid + it * 256;
            if (t < half) s[t] = areg[it];
        }
        __syncthreads();
    }
    if (tid < 128) {
        float a = s[tid];
        Fr[tid] = a;
        sabs += fabsf(a);
        ssq  += a * a;
    }

    double da = (double)sabs, dq = (double)ssq;
    #pragma unroll
    for (int o = 16; o > 0; o >>= 1) {
        da += __shfl_down_sync(0xffffffffu, da, o);
        dq += __shfl_down_sync(0xffffffffu, dq, o);
    }
    const int w = tid >> 5, ln = tid & 31;
    if (ln == 0) { wa[w] = da; wq[w] = dq; }
    __syncthreads();
    if (tid == 0) {
        double A = 0.0, Q = 0.0;
        #pragma unroll
        for (int i = 0; i < 8; i++) { A += wa[i]; Q += wq[i]; }
        g_pabs[r] = A;
        g_psq[r]  = Q;
    }
}

// ---------------- kernel 2: global threshold ----------------
__global__ __launch_bounds__(256) void thr_kernel() {
    __shared__ double wa[8], wq[8];
    const int tid = threadIdx.x;
    double da = 0.0, dq = 0.0;
    for (int i = tid; i < B_ROWS; i += 256) { da += g_pabs[i]; dq += g_psq[i]; }
    #pragma unroll
    for (int o = 16; o > 0; o >>= 1) {
        da += __shfl_down_sync(0xffffffffu, da, o);
        dq += __shfl_down_sync(0xffffffffu, dq, o);
    }
    const int w = tid >> 5, ln = tid & 31;
    if (ln == 0) { wa[w] = da; wq[w] = dq; }
    __syncthreads();
    if (tid == 0) {
        double A = 0.0, Q = 0.0;
        #pragma unroll
        for (int i = 0; i < 8; i++) { A += wa[i]; Q += wq[i]; }
        const double N = (double)B_ROWS * (double)L_DIM;
        double mean = A / N;
        double var  = (Q - N * mean * mean) / (N - 1.0);
        if (var < 0.0) var = 0.0;
        g_thr = (float)(mean + sqrt(var));
    }
}

// ---------------- kernel 3: B transpose + bf16 hi/lo split ----------------
__global__ __launch_bounds__(256) void bconv_kernel(const float* __restrict__ Bm) {
    __shared__ float t[64][65];
    const int n0 = blockIdx.x * 64;
    const int k0 = blockIdx.y * 64;
    for (int idx = threadIdx.x; idx < 4096; idx += 256) {
        int r = idx >> 6, c = idx & 63;           // r = k, c = n
        t[r][c] = Bm[(size_t)(k0 + r) * OUT_DIM + n0 + c];
    }
    __syncthreads();
    for (int idx = threadIdx.x; idx < 4096; idx += 256) {
        int n = idx >> 6, kk = idx & 63;
        float v = t[kk][n];
        __nv_bfloat16 h = __float2bfloat16(v);
        __nv_bfloat16 l = __float2bfloat16(v - __bfloat162float(h));
        size_t o = (size_t)(n0 + n) * L_DIM + k0 + kk;
        g_Bh[o] = h;
        g_Bl[o] = l;
    }
}

// ---------------- kernel 4: HMMA split-bf16 GEMM + mask + ReLU ----------------
// CTA tile 64(m) x 128(n) x 32(k). 8 warps as 2(m) x 4(n), warp tile 32x32.
// smem rows padded to 80B -> conflict-free ldmatrix / cp.async.
#define BM 64
#define BN 128
#define BK 32
#define NST (L_DIM / BK)
#define LDSM_P 80                                 /* bytes per smem row */
#define OFF_AH 0
#define OFF_AL (64 * LDSM_P)
#define OFF_BH (2 * 64 * LDSM_P)
#define OFF_BL (2 * 64 * LDSM_P + 128 * LDSM_P)
#define ST_BYTES (2 * 64 * LDSM_P + 2 * 128 * LDSM_P)   /* 30720 */
#define SMEM_TOTAL (2 * ST_BYTES)                        /* 61440 */

__global__ void __launch_bounds__(256, 2) gemm_kernel(float* __restrict__ out) {
    extern __shared__ char smem[];
    const uint32_t sb = smem_u32(smem);
    const int tid = threadIdx.x;
    const int lane = tid & 31;
    const int wid = tid >> 5;
    const int bm = blockIdx.y * BM;
    const int bn = blockIdx.x * BN;
    const float thr = g_thr;

    const int wm = (wid & 1) * 32;                // warp m-offset in CTA tile
    const int wn = (wid >> 1) * 32;               // warp n-offset

    // A gmem load mapping: 64 rows x 8 chunks(16B); thread -> (row=tid>>3 (+32), chunk=tid&7)
    const int a_r0 = tid >> 3;
    const int a_ch = tid & 7;
    // B cp.async mapping: 128 rows x 4 chunks x {hi,lo}; thread -> row=tid>>1, 2 chunks
    const int b_r  = tid >> 1;
    const int b_c0 = (tid & 1) * 32;              // byte offset of 2-chunk pair

    float acc[2][4][4];
    #pragma unroll
    for (int i = 0; i < 2; i++)
        #pragma unroll
        for (int j = 0; j < 4; j++)
            #pragma unroll
            for (int q = 0; q < 4; q++) acc[i][j][q] = 0.f;

    float4 av0, av1;

    // ---- prologue: stage 0 ----
    {
        const int k0 = 0;
        av0 = *reinterpret_cast<const float4*>(g_F + (size_t)(bm + a_r0) * L_DIM + k0 + a_ch * 4);
        av1 = *reinterpret_cast<const float4*>(g_F + (size_t)(bm + a_r0 + 32) * L_DIM + k0 + a_ch * 4);
        const size_t gb = ((size_t)(bn + b_r) * L_DIM + k0) * 2;
        cp16(sb + OFF_BH + b_r * LDSM_P + b_c0,      (const char*)g_Bh + gb + b_c0);
        cp16(sb + OFF_BH + b_r * LDSM_P + b_c0 + 16, (const char*)g_Bh + gb + b_c0 + 16);
        cp16(sb + OFF_BL + b_r * LDSM_P + b_c0,      (const char*)g_Bl + gb + b_c0);
        cp16(sb + OFF_BL + b_r * LDSM_P + b_c0 + 16, (const char*)g_Bl + gb + b_c0 + 16);
        asm volatile("cp.async.commit_group;" ::: "memory");

        // mask + split + STS stage 0
        float f0[4] = {av0.x, av0.y, av0.z, av0.w};
        float f1[4] = {av1.x, av1.y, av1.z, av1.w};
        #pragma unroll
        for (int q = 0; q < 4; q++) {
            f0[q] = (fabsf(f0[q]) > thr) ? f0[q] : 0.f;
            f1[q] = (fabsf(f1[q]) > thr) ? f1[q] : 0.f;
        }
        uint2 h0, l0, h1, l1;
        h0.x = pack_bf16(f0[0], f0[1]); h0.y = pack_bf16(f0[2], f0[3]);
        h1.x = pack_bf16(f1[0], f1[1]); h1.y = pack_bf16(f1[2], f1[3]);
        l0.x = pack_bf16(f0[0] - __bfloat162float(__float2bfloat16(f0[0])),
                         f0[1] - __bfloat162float(__float2bfloat16(f0[1])));
        l0.y = pack_bf16(f0[2] - __bfloat162float(__float2bfloat16(f0[2])),
                         f0[3] - __bfloat162float(__float2bfloat16(f0[3])));
        l1.x = pack_bf16(f1[0] - __bfloat162float(__float2bfloat16(f1[0])),
                         f1[1] - __bfloat162float(__float2bfloat16(f1[1])));
        l1.y = pack_bf16(f1[2] - __bfloat162float(__float2bfloat16(f1[2])),
                         f1[3] - __bfloat162float(__float2bfloat16(f1[3])));
        *reinterpret_cast<uint2*>(smem + OFF_AH + a_r0 * LDSM_P + a_ch * 8) = h0;
        *reinterpret_cast<uint2*>(smem + OFF_AH + (a_r0 + 32) * LDSM_P + a_ch * 8) = h1;
        *reinterpret_cast<uint2*>(smem + OFF_AL + a_r0 * LDSM_P + a_ch * 8) = l0;
        *reinterpret_cast<uint2*>(smem + OFF_AL + (a_r0 + 32) * LDSM_P + a_ch * 8) = l1;

        asm volatile("cp.async.wait_group 0;" ::: "memory");
        __syncthreads();
    }

    for (int s = 0; s < NST; s++) {
        const int b = s & 1;
        const uint32_t sbb = sb + b * ST_BYTES;
        const bool more = (s + 1 < NST);

        if (more) {
            const int k1 = (s + 1) * BK;
            const int nb = b ^ 1;
            const uint32_t snb = sb + nb * ST_BYTES;
            const size_t gb = ((size_t)(bn + b_r) * L_DIM + k1) * 2;
            cp16(snb + OFF_BH + b_r * LDSM_P + b_c0,      (const char*)g_Bh + gb + b_c0);
            cp16(snb + OFF_BH + b_r * LDSM_P + b_c0 + 16, (const char*)g_Bh + gb + b_c0 + 16);
            cp16(snb + OFF_BL + b_r * LDSM_P + b_c0,      (const char*)g_Bl + gb + b_c0);
            cp16(snb + OFF_BL + b_r * LDSM_P + b_c0 + 16, (const char*)g_Bl + gb + b_c0 + 16);
            asm volatile("cp.async.commit_group;" ::: "memory");
            av0 = *reinterpret_cast<const float4*>(g_F + (size_t)(bm + a_r0) * L_DIM + k1 + a_ch * 4);
            av1 = *reinterpret_cast<const float4*>(g_F + (size_t)(bm + a_r0 + 32) * L_DIM + k1 + a_ch * 4);
        }

        // ---- compute on buffer b ----
        #pragma unroll
        for (int ks = 0; ks < 2; ks++) {
            const uint32_t akb = ks * 32 + ((lane >> 4) << 4);
            const uint32_t arow = wm + (lane & 15);
            const uint32_t bkb = ks * 32 + (((lane >> 3) & 1) << 4);
            const uint32_t brow = wn + ((lane >> 4) << 3) + (lane & 7);

            uint32_t ah[2][4], bh[2][4], bl[2][4], al[2][4];
            ldsm4(ah[0], sbb + OFF_AH + arow * LDSM_P + akb);
            ldsm4(ah[1], sbb + OFF_AH + (arow + 16) * LDSM_P + akb);
            ldsm4(bh[0], sbb + OFF_BH + brow * LDSM_P + bkb);
            ldsm4(bh[1], sbb + OFF_BH + (brow + 16) * LDSM_P + bkb);
            ldsm4(bl[0], sbb + OFF_BL + brow * LDSM_P + bkb);
            ldsm4(bl[1], sbb + OFF_BL + (brow + 16) * LDSM_P + bkb);
            #pragma unroll
            for (int mf = 0; mf < 2; mf++)
                #pragma unroll
                for (int nf = 0; nf < 4; nf++) {
                    mma16816(acc[mf][nf], ah[mf], &bh[nf >> 1][(nf & 1) * 2]);
                    mma16816(acc[mf][nf], ah[mf], &bl[nf >> 1][(nf & 1) * 2]);
                }
            ldsm4(al[0], sbb + OFF_AL + arow * LDSM_P + akb);
            ldsm4(al[1], sbb + OFF_AL + (arow + 16) * LDSM_P + akb);
            #pragma unroll
            for (int mf = 0; mf < 2; mf++)
                #pragma unroll
                for (int nf = 0; nf < 4; nf++)
                    mma16816(acc[mf][nf], al[mf], &bh[nf >> 1][(nf & 1) * 2]);
        }

        if (more) {
            const int nb = b ^ 1;
            char* snb = smem + nb * ST_BYTES;
            float f0[4] = {av0.x, av0.y, av0.z, av0.w};
            float f1[4] = {av1.x, av1.y, av1.z, av1.w};
            #pragma unroll
            for (int q = 0; q < 4; q++) {
                f0[q] = (fabsf(f0[q]) > thr) ? f0[q] : 0.f;
                f1[q] = (fabsf(f1[q]) > thr) ? f1[q] : 0.f;
            }
            uint2 h0, l0, h1, l1;
            h0.x = pack_bf16(f0[0], f0[1]); h0.y = pack_bf16(f0[2], f0[3]);
            h1.x = pack_bf16(f1[0], f1[1]); h1.y = pack_bf16(f1[2], f1[3]);
            l0.x = pack_bf16(f0[0] - __bfloat162float(__float2bfloat16(f0[0])),
                             f0[1] - __bfloat162float(__float2bfloat16(f0[1])));
            l0.y = pack_bf16(f0[2] - __bfloat162float(__float2bfloat16(f0[2])),
                             f0[3] - __bfloat162float(__float2bfloat16(f0[3])));
            l1.x = pack_bf16(f1[0] - __bfloat162float(__float2bfloat16(f1[0])),
                             f1[1] - __bfloat162float(__float2bfloat16(f1[1])));
            l1.y = pack_bf16(f1[2] - __bfloat162float(__float2bfloat16(f1[2])),
                             f1[3] - __bfloat162float(__float2bfloat16(f1[3])));
            *reinterpret_cast<uint2*>(snb + OFF_AH + a_r0 * LDSM_P + a_ch * 8) = h0;
            *reinterpret_cast<uint2*>(snb + OFF_AH + (a_r0 + 32) * LDSM_P + a_ch * 8) = h1;
            *reinterpret_cast<uint2*>(snb + OFF_AL + a_r0 * LDSM_P + a_ch * 8) = l0;
            *reinterpret_cast<uint2*>(snb + OFF_AL + (a_r0 + 32) * LDSM_P + a_ch * 8) = l1;
        }

        asm volatile("cp.async.wait_group 0;" ::: "memory");
        __syncthreads();
    }

    // ---- epilogue: ReLU + store ----
    const int g  = lane >> 2;
    const int tq = lane & 3;
    #pragma unroll
    for (int mf = 0; mf < 2; mf++) {
        #pragma unroll
        for (int nf = 0; nf < 4; nf++) {
            const int m0 = bm + wm + mf * 16 + g;
            const int n0 = bn + wn + nf * 8 + tq * 2;
            float2 v0, v1;
            v0.x = fmaxf(acc[mf][nf][0], 0.f);
            v0.y = fmaxf(acc[mf][nf][1], 0.f);
            v1.x = fmaxf(acc[mf][nf][2], 0.f);
            v1.y = fmaxf(acc[mf][nf][3], 0.f);
            *reinterpret_cast<float2*>(out + (size_t)m0 * OUT_DIM + n0) = v0;
            *reinterpret_cast<float2*>(out + (size_t)(m0 + 8) * OUT_DIM + n0) = v1;
        }
    }
}

// ---------------- launcher ----------------
extern "C" void kernel_launch(void* const* d_in, const int* in_sizes, int n_in,
                              void* d_out, int out_size) {
    const float* x  = (const float*)d_in[0];     // (8192, 1, 4096) fp32
    const float* bm = (const float*)d_in[1];     // (4096, 512) fp32
    float* out = (float*)d_out;                  // (8192, 1, 512) fp32

    cudaFuncSetAttribute(gemm_kernel, cudaFuncAttributeMaxDynamicSharedMemorySize, SMEM_TOTAL);

    haar_kernel<<<B_ROWS, 256>>>(x);
    thr_kernel<<<1, 256>>>();
    bconv_kernel<<<dim3(OUT_DIM / 64, L_DIM / 64), 256>>>(bm);
    gemm_kernel<<<dim3(OUT_DIM / BN, B_ROWS / BM), 256, SMEM_TOTAL>>>(out);
}

// round 8
// speedup vs baseline: 2.3335x; 1.4697x over previous
#include <cuda_runtime.h>
#include <cuda_fp16.h>
#include <cstdint>

#define B_ROWS 8192
#define L_DIM  4096
#define OUT_DIM 512
#define SQRT_HALF 0.7071067811865476f

// ---------------- scratch (static __device__, no allocation) ----------------
__device__ __align__(128) float  g_F[(size_t)B_ROWS * L_DIM];   // fp32 coefficients
__device__ __align__(128) __half g_B16[(size_t)OUT_DIM * L_DIM]; // B^T fp16 [n][k]
__device__ double g_pabs[B_ROWS];
__device__ double g_psq[B_ROWS];
__device__ float  g_thr;

// ---------------- PTX helpers (sm_80-baseline only) ----------------
__device__ __forceinline__ uint32_t smem_u32(const void* p) {
    uint32_t a;
    asm("{ .reg .u64 t; cvta.to.shared.u64 t, %1; cvt.u32.u64 %0, t; }" : "=r"(a) : "l"(p));
    return a;
}
__device__ __forceinline__ void cp16(uint32_t dst, const void* src) {
    asm volatile("cp.async.cg.shared.global [%0], [%1], 16;" :: "r"(dst), "l"(src) : "memory");
}
__device__ __forceinline__ void ldsm4(uint32_t* r, uint32_t addr) {
    asm volatile("ldmatrix.sync.aligned.m8n8.x4.shared.b16 {%0,%1,%2,%3}, [%4];"
                 : "=r"(r[0]), "=r"(r[1]), "=r"(r[2]), "=r"(r[3]) : "r"(addr));
}
__device__ __forceinline__ void mma16816(float* c, const uint32_t* a, const uint32_t* b) {
    asm volatile("mma.sync.aligned.m16n8k16.row.col.f32.f16.f16.f32 "
                 "{%0,%1,%2,%3}, {%4,%5,%6,%7}, {%8,%9}, {%0,%1,%2,%3};"
                 : "+f"(c[0]), "+f"(c[1]), "+f"(c[2]), "+f"(c[3])
                 : "r"(a[0]), "r"(a[1]), "r"(a[2]), "r"(a[3]), "r"(b[0]), "r"(b[1]));
}
__device__ __forceinline__ uint32_t packh(float a, float b) {
    __half2 h = __floats2half2_rn(a, b);
    return *reinterpret_cast<uint32_t*>(&h);
}

// ---------------- kernel 1: Haar DWT + per-row stats ----------------
__global__ __launch_bounds__(256) void haar_kernel(const float* __restrict__ x) {
    __shared__ float s[4096];
    __shared__ double wa[8], wq[8];

    const int r = blockIdx.x;
    const int tid = threadIdx.x;

    const float4* xr = reinterpret_cast<const float4*>(x + (size_t)r * L_DIM);
    float4* s4 = reinterpret_cast<float4*>(s);
    #pragma unroll
    for (int i = 0; i < 4; i++) s4[tid + i * 256] = xr[tid + i * 256];
    __syncthreads();

    float sabs = 0.f, ssq = 0.f;
    float* Fr = g_F + (size_t)r * L_DIM;

    #pragma unroll
    for (int lvl = 0; lvl < 5; lvl++) {
        const int half = 2048 >> lvl;
        float areg[8];
        #pragma unroll
        for (int it = 0; it < 8; it++) {
            const int t = tid + it * 256;
            if (t < half) {
                float2 eo = *reinterpret_cast<const float2*>(&s[2 * t]);
                float d = (eo.x - eo.y) * SQRT_HALF;
                float a = (eo.x + eo.y) * SQRT_HALF;
                Fr[half + t] = d;
                sabs += fabsf(d);
                ssq  += d * d;
                areg[it] = a;
            }
        }
        __syncthreads();
        #pragma unroll
        for (int it = 0; it < 8; it++) {
            const int t = tid + it * 256;
            if (t < half) s[t] = areg[it];
        }
        __syncthreads();
    }
    if (tid < 128) {
        float a = s[tid];
        Fr[tid] = a;
        sabs += fabsf(a);
        ssq  += a * a;
    }

    double da = (double)sabs, dq = (double)ssq;
    #pragma unroll
    for (int o = 16; o > 0; o >>= 1) {
        da += __shfl_down_sync(0xffffffffu, da, o);
        dq += __shfl_down_sync(0xffffffffu, dq, o);
    }
    const int w = tid >> 5, ln = tid & 31;
    if (ln == 0) { wa[w] = da; wq[w] = dq; }
    __syncthreads();
    if (tid == 0) {
        double A = 0.0, Q = 0.0;
        #pragma unroll
        for (int i = 0; i < 8; i++) { A += wa[i]; Q += wq[i]; }
        g_pabs[r] = A;
        g_psq[r]  = Q;
    }
}

// ---------------- kernel 2: global threshold ----------------
__global__ __launch_bounds__(256) void thr_kernel() {
    __shared__ double wa[8], wq[8];
    const int tid = threadIdx.x;
    double da = 0.0, dq = 0.0;
    for (int i = tid; i < B_ROWS; i += 256) { da += g_pabs[i]; dq += g_psq[i]; }
    #pragma unroll
    for (int o = 16; o > 0; o >>= 1) {
        da += __shfl_down_sync(0xffffffffu, da, o);
        dq += __shfl_down_sync(0xffffffffu, dq, o);
    }
    const int w = tid >> 5, ln = tid & 31;
    if (ln == 0) { wa[w] = da; wq[w] = dq; }
    __syncthreads();
    if (tid == 0) {
        double A = 0.0, Q = 0.0;
        #pragma unroll
        for (int i = 0; i < 8; i++) { A += wa[i]; Q += wq[i]; }
        const double N = (double)B_ROWS * (double)L_DIM;
        double mean = A / N;
        double var  = (Q - N * mean * mean) / (N - 1.0);
        if (var < 0.0) var = 0.0;
        g_thr = (float)(mean + sqrt(var));
    }
}

// ---------------- kernel 3: B transpose + fp16 convert ----------------
__global__ __launch_bounds__(256) void bconv_kernel(const float* __restrict__ Bm) {
    __shared__ float t[64][65];
    const int n0 = blockIdx.x * 64;
    const int k0 = blockIdx.y * 64;
    for (int idx = threadIdx.x; idx < 4096; idx += 256) {
        int r = idx >> 6, c = idx & 63;           // r = k, c = n
        t[r][c] = Bm[(size_t)(k0 + r) * OUT_DIM + n0 + c];
    }
    __syncthreads();
    for (int idx = threadIdx.x; idx < 4096; idx += 256) {
        int n = idx >> 6, kk = idx & 63;
        g_B16[(size_t)(n0 + n) * L_DIM + k0 + kk] = __float2half_rn(t[kk][n]);
    }
}

// ---------------- kernel 4: HMMA fp16 2-term GEMM + mask + ReLU ----------------
// CTA 128(m) x 256(n) x 32(k), 512 threads, 16 warps = 4m x 4n, warp tile 32x64.
// Terms: Ah*Bh + Al*Bh  (A = Ah + Al exact fp16 split; only A*(B - fp16(B)) dropped).
#define BM 128
#define BN 256
#define BK 32
#define NST (L_DIM / BK)
#define PAD80 80                                   /* fp16 tile row bytes (ldmatrix-safe) */
#define AF_PITCH 144                               /* fp32 staging row bytes */

#define OFF_AF 0                                   /* 128 x 144 = 18432 */
#define AH_SZ (128 * PAD80)                        /* 10240 */
#define OFF_AH(b) (18432 + (b) * AH_SZ)
#define OFF_AL(b) (38912 + (b) * AH_SZ)
#define BH_SZ (256 * PAD80)                        /* 20480 */
#define OFF_BH(b) (59392 + (b) * BH_SZ)
#define SMEM_TOTAL (59392 + 2 * BH_SZ)             /* 100352 */

__global__ void __launch_bounds__(512, 1) gemm_kernel(float* __restrict__ out) {
    extern __shared__ char smem[];
    const uint32_t sb = smem_u32(smem);
    const int tid = threadIdx.x;
    const int lane = tid & 31;
    const int wid = tid >> 5;
    const int bm = blockIdx.y * BM;
    const int bn = blockIdx.x * BN;
    const float thr = g_thr;

    const int wm = (wid >> 2) * 32;               // warp m-offset
    const int wn = (wid & 3) * 64;                // warp n-offset

    // cp.async mappings
    const int af_r = tid >> 2, af_c = tid & 3;    // A fp32: 128 rows x 8 chunks; 2 chunks/thread
    const int bh_r = tid >> 1, bh_c = (tid & 1) * 2; // B fp16: 256 rows x 4 chunks; 2 chunks/thread

    float acc[2][8][4];
    #pragma unroll
    for (int i = 0; i < 2; i++)
        #pragma unroll
        for (int j = 0; j < 8; j++)
            #pragma unroll
            for (int q = 0; q < 4; q++) acc[i][j][q] = 0.f;

    // ---- prologue: stage 0 loads ----
    {
        const size_t ga = ((size_t)(bm + af_r) * L_DIM) * 4 + af_c * 16;
        cp16(sb + OFF_AF + af_r * AF_PITCH + af_c * 16,      (const char*)g_F + ga);
        cp16(sb + OFF_AF + af_r * AF_PITCH + af_c * 16 + 64, (const char*)g_F + ga + 64);
        const size_t gbv = ((size_t)(bn + bh_r) * L_DIM) * 2 + bh_c * 16;
        cp16(sb + OFF_BH(0) + bh_r * PAD80 + bh_c * 16,      (const char*)g_B16 + gbv);
        cp16(sb + OFF_BH(0) + bh_r * PAD80 + bh_c * 16 + 16, (const char*)g_B16 + gbv + 16);
        asm volatile("cp.async.commit_group;" ::: "memory");
        asm volatile("cp.async.wait_group 0;" ::: "memory");
        __syncthreads();
    }

    for (int s = 0; s < NST; s++) {
        const int b = s & 1;

        // ---- convert stage s: Afp32 -> Ah/Al[b] (mask + exact fp16 split) ----
        {
            #pragma unroll
            for (int h = 0; h < 2; h++) {
                float4 v = *reinterpret_cast<const float4*>(
                    smem + OFF_AF + af_r * AF_PITCH + (af_c + h * 4) * 16);
                v.x = (fabsf(v.x) > thr) ? v.x : 0.f;
                v.y = (fabsf(v.y) > thr) ? v.y : 0.f;
                v.z = (fabsf(v.z) > thr) ? v.z : 0.f;
                v.w = (fabsf(v.w) > thr) ? v.w : 0.f;
                uint2 hi, lo;
                hi.x = packh(v.x, v.y);
                hi.y = packh(v.z, v.w);
                lo.x = packh(v.x - __half2float(__float2half_rn(v.x)),
                             v.y - __half2float(__float2half_rn(v.y)));
                lo.y = packh(v.z - __half2float(__float2half_rn(v.z)),
                             v.w - __half2float(__float2half_rn(v.w)));
                *reinterpret_cast<uint2*>(smem + OFF_AH(b) + af_r * PAD80 + (af_c + h * 4) * 8) = hi;
                *reinterpret_cast<uint2*>(smem + OFF_AL(b) + af_r * PAD80 + (af_c + h * 4) * 8) = lo;
            }
        }
        __syncthreads();

        // ---- prefetch stage s+1 (A fp32 staging + B fp16 into other buffer) ----
        if (s + 1 < NST) {
            const int k1 = (s + 1) * BK;
            const size_t ga = ((size_t)(bm + af_r) * L_DIM + k1) * 4 + af_c * 16;
            cp16(sb + OFF_AF + af_r * AF_PITCH + af_c * 16,      (const char*)g_F + ga);
            cp16(sb + OFF_AF + af_r * AF_PITCH + af_c * 16 + 64, (const char*)g_F + ga + 64);
            const size_t gbv = ((size_t)(bn + bh_r) * L_DIM + k1) * 2 + bh_c * 16;
            cp16(sb + OFF_BH(b ^ 1) + bh_r * PAD80 + bh_c * 16,      (const char*)g_B16 + gbv);
            cp16(sb + OFF_BH(b ^ 1) + bh_r * PAD80 + bh_c * 16 + 16, (const char*)g_B16 + gbv + 16);
            asm volatile("cp.async.commit_group;" ::: "memory");
        }

        // ---- compute on buffer b ----
        const uint32_t sAH = sb + OFF_AH(b);
        const uint32_t sAL = sb + OFF_AL(b);
        const uint32_t sBH = sb + OFF_BH(b);
        #pragma unroll
        for (int ks = 0; ks < 2; ks++) {
            const uint32_t ab = ks * 32 + ((lane >> 4) << 4);
            const uint32_t ar = wm + (lane & 15);
            const uint32_t bb = ks * 32 + (((lane >> 3) & 1) << 4);
            const uint32_t br = ((lane >> 4) << 3) + (lane & 7);

            uint32_t bh[4][4];
            #pragma unroll
            for (int g = 0; g < 4; g++)
                ldsm4(bh[g], sBH + (wn + g * 16 + br) * PAD80 + bb);

            uint32_t ah[2][4];
            ldsm4(ah[0], sAH + ar * PAD80 + ab);
            ldsm4(ah[1], sAH + (ar + 16) * PAD80 + ab);
            #pragma unroll
            for (int mf = 0; mf < 2; mf++)
                #pragma unroll
                for (int g = 0; g < 4; g++) {
                    mma16816(acc[mf][2 * g],     ah[mf], &bh[g][0]);
                    mma16816(acc[mf][2 * g + 1], ah[mf], &bh[g][2]);
                }

            uint32_t al[2][4];
            ldsm4(al[0], sAL + ar * PAD80 + ab);
            ldsm4(al[1], sAL + (ar + 16) * PAD80 + ab);
            #pragma unroll
            for (int mf = 0; mf < 2; mf++)
                #pragma unroll
                for (int g = 0; g < 4; g++) {
                    mma16816(acc[mf][2 * g],     al[mf], &bh[g][0]);
                    mma16816(acc[mf][2 * g + 1], al[mf], &bh[g][2]);
                }
        }

        asm volatile("cp.async.wait_group 0;" ::: "memory");
        __syncthreads();
    }

    // ---- epilogue: ReLU + store ----
    const int g  = lane >> 2;
    const int tq = lane & 3;
    #pragma unroll
    for (int mf = 0; mf < 2; mf++) {
        #pragma unroll
        for (int nf = 0; nf < 8; nf++) {
            const int m0 = bm + wm + mf * 16 + g;
            const int n0 = bn + wn + nf * 8 + tq * 2;
            float2 v0, v1;
            v0.x = fmaxf(acc[mf][nf][0], 0.f);
            v0.y = fmaxf(acc[mf][nf][1], 0.f);
            v1.x = fmaxf(acc[mf][nf][2], 0.f);
            v1.y = fmaxf(acc[mf][nf][3], 0.f);
            *reinterpret_cast<float2*>(out + (size_t)m0 * OUT_DIM + n0) = v0;
            *reinterpret_cast<float2*>(out + (size_t)(m0 + 8) * OUT_DIM + n0) = v1;
        }
    }
}

// ---------------- launcher ----------------
extern "C" void kernel_launch(void* const* d_in, const int* in_sizes, int n_in,
                              void* d_out, int out_size) {
    const float* x  = (const float*)d_in[0];     // (8192, 1, 4096) fp32
    const float* bm = (const float*)d_in[1];     // (4096, 512) fp32
    float* out = (float*)d_out;                  // (8192, 1, 512) fp32

    cudaFuncSetAttribute(gemm_kernel, cudaFuncAttributeMaxDynamicSharedMemorySize, SMEM_TOTAL);

    haar_kernel<<<B_ROWS, 256>>>(x);
    thr_kernel<<<1, 256>>>();
    bconv_kernel<<<dim3(OUT_DIM / 64, L_DIM / 64), 256>>>(bm);
    gemm_kernel<<<dim3(OUT_DIM / BN, B_ROWS / BM), 512, SMEM_TOTAL>>>(out);
}

// round 9
// speedup vs baseline: 3.2258x; 1.3824x over previous
#include <cuda_runtime.h>
#include <cuda_fp16.h>
#include <cstdint>

#define B_ROWS 8192
#define L_DIM  4096
#define OUT_DIM 512
#define SQRT_HALF 0.7071067811865476f

// ---------------- scratch (static __device__, no allocation) ----------------
__device__ __align__(128) float  g_F[(size_t)B_ROWS * L_DIM];    // fp32 coefficients
__device__ __align__(128) __half g_B16[(size_t)OUT_DIM * L_DIM]; // B^T fp16 [n][k]
__device__ double g_pabs[B_ROWS];
__device__ double g_psq[B_ROWS];
__device__ float  g_thr;

// ---------------- PTX helpers (sm_80-baseline only) ----------------
__device__ __forceinline__ uint32_t smem_u32(const void* p) {
    uint32_t a;
    asm("{ .reg .u64 t; cvta.to.shared.u64 t, %1; cvt.u32.u64 %0, t; }" : "=r"(a) : "l"(p));
    return a;
}
__device__ __forceinline__ void cp16(uint32_t dst, const void* src) {
    asm volatile("cp.async.cg.shared.global [%0], [%1], 16;" :: "r"(dst), "l"(src) : "memory");
}
__device__ __forceinline__ void ldsm4(uint32_t* r, uint32_t addr) {
    asm volatile("ldmatrix.sync.aligned.m8n8.x4.shared.b16 {%0,%1,%2,%3}, [%4];"
                 : "=r"(r[0]), "=r"(r[1]), "=r"(r[2]), "=r"(r[3]) : "r"(addr));
}
__device__ __forceinline__ void mma16816(float* c, const uint32_t* a, const uint32_t* b) {
    asm volatile("mma.sync.aligned.m16n8k16.row.col.f32.f16.f16.f32 "
                 "{%0,%1,%2,%3}, {%4,%5,%6,%7}, {%8,%9}, {%0,%1,%2,%3};"
                 : "+f"(c[0]), "+f"(c[1]), "+f"(c[2]), "+f"(c[3])
                 : "r"(a[0]), "r"(a[1]), "r"(a[2]), "r"(a[3]), "r"(b[0]), "r"(b[1]));
}
__device__ __forceinline__ uint32_t packh(float a, float b) {
    __half2 h = __floats2half2_rn(a, b);
    return *reinterpret_cast<uint32_t*>(&h);
}

// ---------------- kernel 1: Haar DWT + per-row stats ----------------
__global__ __launch_bounds__(256) void haar_kernel(const float* __restrict__ x) {
    __shared__ float s[4096];
    __shared__ double wa[8], wq[8];

    const int r = blockIdx.x;
    const int tid = threadIdx.x;

    const float4* xr = reinterpret_cast<const float4*>(x + (size_t)r * L_DIM);
    float4* s4 = reinterpret_cast<float4*>(s);
    #pragma unroll
    for (int i = 0; i < 4; i++) s4[tid + i * 256] = xr[tid + i * 256];
    __syncthreads();

    float sabs = 0.f, ssq = 0.f;
    float* Fr = g_F + (size_t)r * L_DIM;

    #pragma unroll
    for (int lvl = 0; lvl < 5; lvl++) {
        const int half = 2048 >> lvl;
        float areg[8];
        #pragma unroll
        for (int it = 0; it < 8; it++) {
            const int t = tid + it * 256;
            if (t < half) {
                float2 eo = *reinterpret_cast<const float2*>(&s[2 * t]);
                float d = (eo.x - eo.y) * SQRT_HALF;
                float a = (eo.x + eo.y) * SQRT_HALF;
                Fr[half + t] = d;
                sabs += fabsf(d);
                ssq  += d * d;
                areg[it] = a;
            }
        }
        __syncthreads();
        #pragma unroll
        for (int it = 0; it < 8; it++) {
            const int t = tid + it * 256;
            if (t < half) s[t] = areg[it];
        }
        __syncthreads();
    }
    if (tid < 128) {
        float a = s[tid];
        Fr[tid] = a;
        sabs += fabsf(a);
        ssq  += a * a;
    }

    double da = (double)sabs, dq = (double)ssq;
    #pragma unroll
    for (int o = 16; o > 0; o >>= 1) {
        da += __shfl_down_sync(0xffffffffu, da, o);
        dq += __shfl_down_sync(0xffffffffu, dq, o);
    }
    const int w = tid >> 5, ln = tid & 31;
    if (ln == 0) { wa[w] = da; wq[w] = dq; }
    __syncthreads();
    if (tid == 0) {
        double A = 0.0, Q = 0.0;
        #pragma unroll
        for (int i = 0; i < 8; i++) { A += wa[i]; Q += wq[i]; }
        g_pabs[r] = A;
        g_psq[r]  = Q;
    }
}

// ---------------- kernel 2: global threshold ----------------
__global__ __launch_bounds__(256) void thr_kernel() {
    __shared__ double wa[8], wq[8];
    const int tid = threadIdx.x;
    double da = 0.0, dq = 0.0;
    for (int i = tid; i < B_ROWS; i += 256) { da += g_pabs[i]; dq += g_psq[i]; }
    #pragma unroll
    for (int o = 16; o > 0; o >>= 1) {
        da += __shfl_down_sync(0xffffffffu, da, o);
        dq += __shfl_down_sync(0xffffffffu, dq, o);
    }
    const int w = tid >> 5, ln = tid & 31;
    if (ln == 0) { wa[w] = da; wq[w] = dq; }
    __syncthreads();
    if (tid == 0) {
        double A = 0.0, Q = 0.0;
        #pragma unroll
        for (int i = 0; i < 8; i++) { A += wa[i]; Q += wq[i]; }
        const double N = (double)B_ROWS * (double)L_DIM;
        double mean = A / N;
        double var  = (Q - N * mean * mean) / (N - 1.0);
        if (var < 0.0) var = 0.0;
        g_thr = (float)(mean + sqrt(var));
    }
}

// ---------------- kernel 3: B transpose + fp16 convert ----------------
__global__ __launch_bounds__(256) void bconv_kernel(const float* __restrict__ Bm) {
    __shared__ float t[64][65];
    const int n0 = blockIdx.x * 64;
    const int k0 = blockIdx.y * 64;
    for (int idx = threadIdx.x; idx < 4096; idx += 256) {
        int r = idx >> 6, c = idx & 63;           // r = k, c = n
        t[r][c] = Bm[(size_t)(k0 + r) * OUT_DIM + n0 + c];
    }
    __syncthreads();
    for (int idx = threadIdx.x; idx < 4096; idx += 256) {
        int n = idx >> 6, kk = idx & 63;
        g_B16[(size_t)(n0 + n) * L_DIM + k0 + kk] = __float2half_rn(t[kk][n]);
    }
}

// ---------------- kernel 4: pure-fp16 HMMA GEMM + mask + ReLU ----------------
// CTA 128(m) x 256(n) x 64(k), 512 threads, 16 warps = 4m x 4n, warp tile 32x64.
// A masked fp32 -> fp16 directly (LDG->regs->cvt->STS), B fp16 via cp.async.
// One __syncthreads per stage; convert interleaved mid-compute.
#define BM 128
#define BN 256
#define BK 64
#define NST (L_DIM / BK)
#define PADA 144                                  /* A fp16 tile row bytes */
#define PADB 144                                  /* B fp16 tile row bytes */
#define AH_SZ (128 * PADA)                        /* 18432 */
#define OFF_AH(b) ((b) * AH_SZ)
#define B_SZ (256 * PADB)                         /* 36864 */
#define OFF_B(b) (2 * AH_SZ + (b) * B_SZ)
#define SMEM_TOTAL (2 * AH_SZ + 2 * B_SZ)         /* 110592 */

__global__ void __launch_bounds__(512, 1) gemm_kernel(float* __restrict__ out) {
    extern __shared__ char smem[];
    const uint32_t sb = smem_u32(smem);
    const int tid = threadIdx.x;
    const int lane = tid & 31;
    const int wid = tid >> 5;
    const int bm = blockIdx.y * BM;
    const int bn = blockIdx.x * BN;
    const float thr = g_thr;

    const int wm = (wid >> 2) * 32;               // warp m-offset
    const int wn = (wid & 3) * 64;                // warp n-offset

    // A LDG mapping: 128 rows x 64 cols fp32; thread -> row tid>>2, 4 chunks of 4 floats
    const int af_r = tid >> 2;
    const int af_c = tid & 3;                     // chunk base; chunks at af_c + 4*i
    // B cp.async mapping: 256 rows x 128B; thread -> row tid>>1, 4 chunks of 16B
    const int bh_r = tid >> 1;
    const int bh_c = (tid & 1) * 64;              // byte base of 4-chunk run

    float acc[2][8][4];
    #pragma unroll
    for (int i = 0; i < 2; i++)
        #pragma unroll
        for (int j = 0; j < 8; j++)
            #pragma unroll
            for (int q = 0; q < 4; q++) acc[i][j][q] = 0.f;

    const float* Abase = g_F + (size_t)(bm + af_r) * L_DIM + af_c * 4;
    const char*  Bbase = (const char*)(g_B16 + (size_t)(bn + bh_r) * L_DIM) + bh_c;

    // ---- prologue: fill buffer 0 ----
    {
        float4 av[4];
        #pragma unroll
        for (int i = 0; i < 4; i++) av[i] = *reinterpret_cast<const float4*>(Abase + i * 16);
        #pragma unroll
        for (int i = 0; i < 4; i++) {
            cp16(sb + OFF_B(0) + bh_r * PADB + bh_c + i * 16, Bbase + i * 16);
        }
        asm volatile("cp.async.commit_group;" ::: "memory");
        #pragma unroll
        for (int i = 0; i < 4; i++) {
            float xx = (fabsf(av[i].x) > thr) ? av[i].x : 0.f;
            float yy = (fabsf(av[i].y) > thr) ? av[i].y : 0.f;
            float zz = (fabsf(av[i].z) > thr) ? av[i].z : 0.f;
            float ww = (fabsf(av[i].w) > thr) ? av[i].w : 0.f;
            uint2 h;
            h.x = packh(xx, yy);
            h.y = packh(zz, ww);
            *reinterpret_cast<uint2*>(smem + OFF_AH(0) + af_r * PADA + (af_c + 4 * i) * 8) = h;
        }
        asm volatile("cp.async.wait_group 0;" ::: "memory");
        __syncthreads();
    }

    for (int s = 0; s < NST; s++) {
        const int b = s & 1;
        const bool more = (s + 1 < NST);
        const uint32_t sAH = sb + OFF_AH(b);
        const uint32_t sBH = sb + OFF_B(b);

        float4 av[4];
        if (more) {
            const int k1 = (s + 1) * BK;
            #pragma unroll
            for (int i = 0; i < 4; i++)
                av[i] = *reinterpret_cast<const float4*>(Abase + k1 + i * 16);
            #pragma unroll
            for (int i = 0; i < 4; i++)
                cp16(sb + OFF_B(b ^ 1) + bh_r * PADB + bh_c + i * 16,
                     Bbase + (size_t)k1 * 2 + i * 16);
            asm volatile("cp.async.commit_group;" ::: "memory");
        }

        uint2 hp[4];

        #pragma unroll
        for (int ks = 0; ks < 4; ks++) {
            const uint32_t ab = ks * 32 + ((lane >> 4) << 4);
            const uint32_t ar = wm + (lane & 15);
            const uint32_t bb = ks * 32 + (((lane >> 3) & 1) << 4);
            const uint32_t br = ((lane >> 4) << 3) + (lane & 7);

            uint32_t bh[4][4];
            #pragma unroll
            for (int g = 0; g < 4; g++)
                ldsm4(bh[g], sBH + (wn + g * 16 + br) * PADB + bb);

            uint32_t ah[2][4];
            ldsm4(ah[0], sAH + ar * PADA + ab);
            ldsm4(ah[1], sAH + (ar + 16) * PADA + ab);

            #pragma unroll
            for (int mf = 0; mf < 2; mf++)
                #pragma unroll
                for (int g = 0; g < 4; g++) {
                    mma16816(acc[mf][2 * g],     ah[mf], &bh[g][0]);
                    mma16816(acc[mf][2 * g + 1], ah[mf], &bh[g][2]);
                }

            // interleave the A convert for stage s+1 between compute chunks
            if (ks == 1 && more) {
                #pragma unroll
                for (int i = 0; i < 4; i++) {
                    float xx = (fabsf(av[i].x) > thr) ? av[i].x : 0.f;
                    float yy = (fabsf(av[i].y) > thr) ? av[i].y : 0.f;
                    float zz = (fabsf(av[i].z) > thr) ? av[i].z : 0.f;
                    float ww = (fabsf(av[i].w) > thr) ? av[i].w : 0.f;
                    hp[i].x = packh(xx, yy);
                    hp[i].y = packh(zz, ww);
                }
            }
        }

        if (more) {
            char* dst = smem + OFF_AH(b ^ 1) + af_r * PADA;
            #pragma unroll
            for (int i = 0; i < 4; i++)
                *reinterpret_cast<uint2*>(dst + (af_c + 4 * i) * 8) = hp[i];
            asm volatile("cp.async.wait_group 0;" ::: "memory");
        }
        __syncthreads();
    }

    // ---- epilogue: ReLU + store ----
    const int g  = lane >> 2;
    const int tq = lane & 3;
    #pragma unroll
    for (int mf = 0; mf < 2; mf++) {
        #pragma unroll
        for (int nf = 0; nf < 8; nf++) {
            const int m0 = bm + wm + mf * 16 + g;
            const int n0 = bn + wn + nf * 8 + tq * 2;
            float2 v0, v1;
            v0.x = fmaxf(acc[mf][nf][0], 0.f);
            v0.y = fmaxf(acc[mf][nf][1], 0.f);
            v1.x = fmaxf(acc[mf][nf][2], 0.f);
            v1.y = fmaxf(acc[mf][nf][3], 0.f);
            *reinterpret_cast<float2*>(out + (size_t)m0 * OUT_DIM + n0) = v0;
            *reinterpret_cast<float2*>(out + (size_t)(m0 + 8) * OUT_DIM + n0) = v1;
        }
    }
}

// ---------------- launcher ----------------
extern "C" void kernel_launch(void* const* d_in, const int* in_sizes, int n_in,
                              void* d_out, int out_size) {
    const float* x  = (const float*)d_in[0];     // (8192, 1, 4096) fp32
    const float* bm = (const float*)d_in[1];     // (4096, 512) fp32
    float* out = (float*)d_out;                  // (8192, 1, 512) fp32

    cudaFuncSetAttribute(gemm_kernel, cudaFuncAttributeMaxDynamicSharedMemorySize, SMEM_TOTAL);

    haar_kernel<<<B_ROWS, 256>>>(x);
    thr_kernel<<<1, 256>>>();
    bconv_kernel<<<dim3(OUT_DIM / 64, L_DIM / 64), 256>>>(bm);
    gemm_kernel<<<dim3(OUT_DIM / BN, B_ROWS / BM), 512, SMEM_TOTAL>>>(out);
}